// round 1
// baseline (speedup 1.0000x reference)
#include <cuda_runtime.h>
#include <math.h>

#define NN 1000
#define FF 64
#define BTOT 192          // B*T
#define EE 16000
#define NTERMS 9
#define KC (NTERMS*FF)    // 576
#define MROWS (BTOT*NN)   // 192000
#define LDIM 768000       // T*N*F
#define CC 10
#define BB 16
#define LN_EPS 1e-5f

// ---------------- static device scratch ----------------
__device__ float g_basis[(size_t)MROWS * KC];   // 442 MB: 9 Chebyshev terms, interleaved
__device__ float g_hn[(size_t)MROWS * FF];      // 49 MB: post-LN hidden
__device__ float g_Wcat[KC * 128];              // stacked weights (z|h)
__device__ int   g_cnt_src[NN], g_cnt_dst[NN];
__device__ int   g_fill_src[NN], g_fill_dst[NN];
__device__ int   g_ptr_src[NN + 1], g_ptr_dst[NN + 1];
__device__ int   g_idx_dst[EE];                 // grouped by dst, stores src
__device__ float g_w_dst[EE];                   // 1/deg_out[src] per edge
__device__ int   g_idx_src[EE];                 // grouped by src, stores dst
__device__ float g_inv_in[NN], g_inv_out[NN];

// ---------------- CSR construction ----------------
__global__ void init_counts_kernel() {
    int i = blockIdx.x * blockDim.x + threadIdx.x;
    if (i < NN) {
        g_cnt_src[i] = 0; g_cnt_dst[i] = 0;
        g_fill_src[i] = 0; g_fill_dst[i] = 0;
    }
}

__global__ void degree_kernel(const int* __restrict__ ei) {
    int e = blockIdx.x * blockDim.x + threadIdx.x;
    if (e < EE) {
        atomicAdd(&g_cnt_src[ei[e]], 1);
        atomicAdd(&g_cnt_dst[ei[EE + e]], 1);
    }
}

__global__ void scan_kernel() {
    if (threadIdx.x == 0) {
        int s = 0;
        for (int n = 0; n < NN; n++) { g_ptr_src[n] = s; s += g_cnt_src[n]; }
        g_ptr_src[NN] = s;
        s = 0;
        for (int n = 0; n < NN; n++) { g_ptr_dst[n] = s; s += g_cnt_dst[n]; }
        g_ptr_dst[NN] = s;
    }
    for (int n = threadIdx.x; n < NN; n += blockDim.x) {
        g_inv_out[n] = 1.0f / (float)g_cnt_src[n];
        g_inv_in[n]  = 1.0f / (float)g_cnt_dst[n];
    }
}

__global__ void fill_kernel(const int* __restrict__ ei) {
    int e = blockIdx.x * blockDim.x + threadIdx.x;
    if (e < EE) {
        int s = ei[e], d = ei[EE + e];
        int p = atomicAdd(&g_fill_dst[d], 1);
        int slot = g_ptr_dst[d] + p;
        g_idx_dst[slot] = s;
        g_w_dst[slot] = g_inv_out[s];
        int q = atomicAdd(&g_fill_src[s], 1);
        g_idx_src[g_ptr_src[s] + q] = d;
    }
}

// ---------------- weight stacking ----------------
// Wcat[kk][j], kk = term*64 + ci, j in [0,128): j<64 -> z-output, j>=64 -> h-output.
// h0 == 0, so only input channels [0,64) of the (2F,F) weight slabs matter.
__global__ void wcat_kernel(const float* __restrict__ Wz, const float* __restrict__ Wh) {
    int t = blockIdx.x * blockDim.x + threadIdx.x;
    if (t >= KC * 128) return;
    int kk = t >> 7;            // [0,576)
    int j  = t & 127;
    int term = kk / FF;
    int ci   = kk % FF;
    const float* W = (j < FF) ? Wz : Wh;
    int co = (j < FF) ? j : j - FF;
    float v;
    if (term == 0) {
        // Tx0 gets both directions' k=0 weight
        v = W[((0 * 5 + 0) * 128 + ci) * 64 + co] + W[((1 * 5 + 0) * 128 + ci) * 64 + co];
    } else if (term <= 4) {
        v = W[((0 * 5 + term) * 128 + ci) * 64 + co];
    } else {
        v = W[((1 * 5 + (term - 4)) * 128 + ci) * 64 + co];
    }
    g_Wcat[kk * 128 + j] = v;
}

// ---------------- basis term 0 = X ----------------
__global__ void copy_t0_kernel(const float* __restrict__ x) {
    int i = blockIdx.x * blockDim.x + threadIdx.x;
    if (i < MROWS * FF) {
        int r = i >> 6, f = i & 63;
        g_basis[(size_t)r * KC + f] = x[i];
    }
}

// ---------------- sparse propagation ----------------
// out-direction: out[n] = alpha * sum_{e: dst=n} (1/deg_out[src_e]) * in[src_e]  (- sub)
__global__ void prop_out_kernel(int term_in, int term_out, int term_sub, float alpha) {
    int n  = blockIdx.x % NN;
    int bt = blockIdx.x / NN;
    int f  = threadIdx.x;
    int b0 = g_ptr_dst[n], b1 = g_ptr_dst[n + 1];
    const float* base = g_basis + (size_t)bt * NN * KC + term_in * FF + f;
    float acc = 0.f;
    for (int e = b0; e < b1; e++)
        acc += g_w_dst[e] * base[(size_t)g_idx_dst[e] * KC];
    float res = alpha * acc;
    float* orow = g_basis + (size_t)(bt * NN + n) * KC;
    if (term_sub >= 0) res -= orow[term_sub * FF + f];
    orow[term_out * FF + f] = res;
}

// in-direction: out[n] = alpha * (1/deg_in[n]) * sum_{e: src=n} in[dst_e]  (- sub)
__global__ void prop_in_kernel(int term_in, int term_out, int term_sub, float alpha) {
    int n  = blockIdx.x % NN;
    int bt = blockIdx.x / NN;
    int f  = threadIdx.x;
    int b0 = g_ptr_src[n], b1 = g_ptr_src[n + 1];
    const float* base = g_basis + (size_t)bt * NN * KC + term_in * FF + f;
    float acc = 0.f;
    for (int e = b0; e < b1; e++)
        acc += base[(size_t)g_idx_src[e] * KC];
    float res = alpha * g_inv_in[n] * acc;
    float* orow = g_basis + (size_t)(bt * NN + n) * KC;
    if (term_sub >= 0) res -= orow[term_sub * FF + f];
    orow[term_out * FF + f] = res;
}

// ---------------- fused GEMM (192000x576 @ 576x128) + gate + LayerNorm ----------------
#define GM 64
#define GK 16
__global__ void __launch_bounds__(256) gemm_epilogue_kernel(
    const float* __restrict__ bz, const float* __restrict__ bh,
    const float* __restrict__ lng, const float* __restrict__ lnb)
{
    __shared__ float As[GM][GK + 1];
    __shared__ float Bs[GK][128];
    __shared__ float Cs[GM][128];

    int block_row = blockIdx.x * GM;
    int tid = threadIdx.x;
    int ty = tid >> 4;      // 0..15 -> rows ty*4..+3
    int tx = tid & 15;      // 0..15 -> cols tx*8..+7

    float acc[4][8];
#pragma unroll
    for (int i = 0; i < 4; i++)
#pragma unroll
        for (int j = 0; j < 8; j++) acc[i][j] = 0.f;

    for (int k0 = 0; k0 < KC; k0 += GK) {
        // load A tile: 64 x 16
#pragma unroll
        for (int i = 0; i < 4; i++) {
            int lin = tid + i * 256;
            int r = lin >> 4, c = lin & 15;
            As[r][c] = g_basis[(size_t)(block_row + r) * KC + k0 + c];
        }
        // load B tile: 16 x 128
#pragma unroll
        for (int i = 0; i < 8; i++) {
            int lin = tid + i * 256;
            int r = lin >> 7, c = lin & 127;
            Bs[r][c] = g_Wcat[(k0 + r) * 128 + c];
        }
        __syncthreads();
#pragma unroll
        for (int kk = 0; kk < GK; kk++) {
            float a[4];
#pragma unroll
            for (int i = 0; i < 4; i++) a[i] = As[ty * 4 + i][kk];
            float4 b0 = *reinterpret_cast<const float4*>(&Bs[kk][tx * 8]);
            float4 b1 = *reinterpret_cast<const float4*>(&Bs[kk][tx * 8 + 4]);
            float b[8] = {b0.x, b0.y, b0.z, b0.w, b1.x, b1.y, b1.z, b1.w};
#pragma unroll
            for (int i = 0; i < 4; i++)
#pragma unroll
                for (int j = 0; j < 8; j++) acc[i][j] += a[i] * b[j];
        }
        __syncthreads();
    }

    // stage raw GEMM output (+bias) to shared
#pragma unroll
    for (int i = 0; i < 4; i++) {
#pragma unroll
        for (int j = 0; j < 8; j++) {
            int col = tx * 8 + j;
            float bias = (col < FF) ? bz[col] : bh[col - FF];
            Cs[ty * 4 + i][col] = acc[i][j] + bias;
        }
    }
    __syncthreads();

    // epilogue: each warp handles 8 rows; lane covers f = lane and f = lane+32
    int w = tid >> 5, lane = tid & 31;
#pragma unroll
    for (int s = 0; s < 8; s++) {
        int r = w * 8 + s;
        float vz0 = Cs[r][lane],      vh0 = Cs[r][64 + lane];
        float vz1 = Cs[r][lane + 32], vh1 = Cs[r][96 + lane];
        float z0 = 1.f / (1.f + expf(-vz0));
        float z1 = 1.f / (1.f + expf(-vz1));
        float g0 = fmaxf(0.f, (1.f - z0) * tanhf(vh0));
        float g1 = fmaxf(0.f, (1.f - z1) * tanhf(vh1));
        float sum = g0 + g1, sq = g0 * g0 + g1 * g1;
#pragma unroll
        for (int o = 16; o; o >>= 1) {
            sum += __shfl_xor_sync(0xffffffffu, sum, o);
            sq  += __shfl_xor_sync(0xffffffffu, sq, o);
        }
        float mu  = sum * (1.f / 64.f);
        float var = fmaxf(sq * (1.f / 64.f) - mu * mu, 0.f);
        float rstd = rsqrtf(var + LN_EPS);
        size_t row = (size_t)(block_row + r) * FF;
        g_hn[row + lane]      = (g0 - mu) * rstd * lng[lane]      + lnb[lane];
        g_hn[row + lane + 32] = (g1 - mu) * rstd * lng[lane + 32] + lnb[lane + 32];
    }
}

// ---------------- final linear head ----------------
__global__ void out_init_kernel(float* __restrict__ out, const float* __restrict__ lb) {
    int i = threadIdx.x;
    if (i < BB * CC) out[i] = lb[i % CC];
}

#define CH 1024
__global__ void __launch_bounds__(256) final_linear_kernel(
    const float* __restrict__ lin_w, float* __restrict__ out)
{
    __shared__ float ws[CC][CH];
    __shared__ float red[8][CC];
    int base = blockIdx.x * CH;   // 750 blocks * 1024 = 768000
    int tid = threadIdx.x;
    for (int i = tid; i < CC * CH; i += 256) {
        int c = i / CH, o = i % CH;
        ws[c][o] = lin_w[(size_t)c * LDIM + base + o];
    }
    __syncthreads();
    int w = tid >> 5, lane = tid & 31;
    for (int b = 0; b < BB; b++) {
        float a[CC];
#pragma unroll
        for (int c = 0; c < CC; c++) a[c] = 0.f;
        const float* hb = g_hn + (size_t)b * LDIM + base;
        for (int i = tid; i < CH; i += 256) {
            float hv = hb[i];
#pragma unroll
            for (int c = 0; c < CC; c++) a[c] += hv * ws[c][i];
        }
#pragma unroll
        for (int o = 16; o; o >>= 1)
#pragma unroll
            for (int c = 0; c < CC; c++) a[c] += __shfl_down_sync(0xffffffffu, a[c], o);
        if (lane == 0)
#pragma unroll
            for (int c = 0; c < CC; c++) red[w][c] = a[c];
        __syncthreads();
        if (tid < CC) {
            float s = 0.f;
#pragma unroll
            for (int ww = 0; ww < 8; ww++) s += red[ww][tid];
            atomicAdd(&out[b * CC + tid], s);
        }
        __syncthreads();
    }
}

// ---------------- launch ----------------
extern "C" void kernel_launch(void* const* d_in, const int* in_sizes, int n_in,
                              void* d_out, int out_size) {
    const float* x    = (const float*)d_in[0];
    const int*   ei   = (const int*)d_in[1];
    const float* Wz   = (const float*)d_in[2];
    const float* bz   = (const float*)d_in[3];
    // d_in[4], d_in[5] = W_r, b_r -> dead code (h0 == 0)
    const float* Wh   = (const float*)d_in[6];
    const float* bh   = (const float*)d_in[7];
    const float* lng  = (const float*)d_in[8];
    const float* lnb  = (const float*)d_in[9];
    const float* linw = (const float*)d_in[10];
    const float* linb = (const float*)d_in[11];
    float* out = (float*)d_out;

    init_counts_kernel<<<(NN + 255) / 256, 256>>>();
    degree_kernel<<<(EE + 255) / 256, 256>>>(ei);
    scan_kernel<<<1, 256>>>();
    fill_kernel<<<(EE + 255) / 256, 256>>>(ei);
    wcat_kernel<<<(KC * 128 + 255) / 256, 256>>>(Wz, Wh);
    copy_t0_kernel<<<(MROWS * FF + 255) / 256, 256>>>(x);

    int nb = BTOT * NN;
    // terms: 0=X, 1..4 = out-chain, 5..8 = in-chain (reference's Tx0 shift uses out-chain history)
    prop_out_kernel<<<nb, FF>>>(0, 1, -1, 1.0f);
    prop_in_kernel <<<nb, FF>>>(0, 5, -1, 1.0f);
    prop_out_kernel<<<nb, FF>>>(1, 2, 0, 2.0f);
    prop_in_kernel <<<nb, FF>>>(5, 6, 0, 2.0f);
    prop_out_kernel<<<nb, FF>>>(2, 3, 1, 2.0f);
    prop_in_kernel <<<nb, FF>>>(6, 7, 1, 2.0f);
    prop_out_kernel<<<nb, FF>>>(3, 4, 2, 2.0f);
    prop_in_kernel <<<nb, FF>>>(7, 8, 2, 2.0f);

    gemm_epilogue_kernel<<<MROWS / GM, 256>>>(bz, bh, lng, lnb);

    out_init_kernel<<<1, 256>>>(out, linb);
    final_linear_kernel<<<LDIM / CH, 256>>>(linw, out);
}

// round 2
// speedup vs baseline: 1.4889x; 1.4889x over previous
#include <cuda_runtime.h>
#include <math.h>
#include <stdint.h>

#define NN 1000
#define FF 64
#define BTOT 192          // B*T
#define EE 16000
#define NTERMS 9
#define KC (NTERMS*FF)    // 576
#define MROWS (BTOT*NN)   // 192000
#define LDIM 768000       // T*N*F
#define CC 10
#define BB 16
#define LN_EPS 1e-5f

// ---------------- static device scratch ----------------
__device__ float g_basis[(size_t)MROWS * KC];   // 442 MB: 9 Chebyshev terms, interleaved
__device__ float g_hn[(size_t)MROWS * FF];      // 49 MB: post-LN hidden
__device__ float g_Wcat[KC * 128];              // stacked weights (z|h), tf32-rounded
__device__ int   g_cnt_src[NN], g_cnt_dst[NN];
__device__ int   g_fill_src[NN], g_fill_dst[NN];
__device__ int   g_ptr_src[NN + 1], g_ptr_dst[NN + 1];
__device__ int   g_idx_dst[EE];                 // grouped by dst, stores src
__device__ float g_w_dst[EE];                   // 1/deg_out[src] per edge
__device__ int   g_idx_src[EE];                 // grouped by src, stores dst
__device__ float g_inv_in[NN], g_inv_out[NN];

__device__ __forceinline__ uint32_t f2tf32(float f) {
    uint32_t u;
    asm("cvt.rna.tf32.f32 %0, %1;" : "=r"(u) : "f"(f));
    return u;
}

__device__ __forceinline__ void mma_tf32(float c[4], const uint32_t a[4],
                                         uint32_t b0, uint32_t b1) {
    asm volatile(
        "mma.sync.aligned.m16n8k8.row.col.f32.tf32.tf32.f32 "
        "{%0,%1,%2,%3}, {%4,%5,%6,%7}, {%8,%9}, {%0,%1,%2,%3};"
        : "+f"(c[0]), "+f"(c[1]), "+f"(c[2]), "+f"(c[3])
        : "r"(a[0]), "r"(a[1]), "r"(a[2]), "r"(a[3]), "r"(b0), "r"(b1));
}

// ---------------- CSR construction ----------------
__global__ void init_counts_kernel() {
    int i = blockIdx.x * blockDim.x + threadIdx.x;
    if (i < NN) {
        g_cnt_src[i] = 0; g_cnt_dst[i] = 0;
        g_fill_src[i] = 0; g_fill_dst[i] = 0;
    }
}

__global__ void degree_kernel(const int* __restrict__ ei) {
    int e = blockIdx.x * blockDim.x + threadIdx.x;
    if (e < EE) {
        atomicAdd(&g_cnt_src[ei[e]], 1);
        atomicAdd(&g_cnt_dst[ei[EE + e]], 1);
    }
}

__global__ void scan_kernel() {
    if (threadIdx.x == 0) {
        int s = 0;
        for (int n = 0; n < NN; n++) { g_ptr_src[n] = s; s += g_cnt_src[n]; }
        g_ptr_src[NN] = s;
        s = 0;
        for (int n = 0; n < NN; n++) { g_ptr_dst[n] = s; s += g_cnt_dst[n]; }
        g_ptr_dst[NN] = s;
    }
    for (int n = threadIdx.x; n < NN; n += blockDim.x) {
        g_inv_out[n] = 1.0f / (float)g_cnt_src[n];
        g_inv_in[n]  = 1.0f / (float)g_cnt_dst[n];
    }
}

__global__ void fill_kernel(const int* __restrict__ ei) {
    int e = blockIdx.x * blockDim.x + threadIdx.x;
    if (e < EE) {
        int s = ei[e], d = ei[EE + e];
        int p = atomicAdd(&g_fill_dst[d], 1);
        int slot = g_ptr_dst[d] + p;
        g_idx_dst[slot] = s;
        g_w_dst[slot] = g_inv_out[s];
        int q = atomicAdd(&g_fill_src[s], 1);
        g_idx_src[g_ptr_src[s] + q] = d;
    }
}

// ---------------- weight stacking ----------------
// Wcat[kk][j], kk = term*64 + ci, j in [0,128): j<64 -> z-output, j>=64 -> h-output.
// h0 == 0, so only input channels [0,64) of the (2F,F) weight slabs matter.
// Stored tf32-rounded (consumed by tensor-core GEMM).
__global__ void wcat_kernel(const float* __restrict__ Wz, const float* __restrict__ Wh) {
    int t = blockIdx.x * blockDim.x + threadIdx.x;
    if (t >= KC * 128) return;
    int kk = t >> 7;            // [0,576)
    int j  = t & 127;
    int term = kk / FF;
    int ci   = kk % FF;
    const float* W = (j < FF) ? Wz : Wh;
    int co = (j < FF) ? j : j - FF;
    float v;
    if (term == 0) {
        v = W[((0 * 5 + 0) * 128 + ci) * 64 + co] + W[((1 * 5 + 0) * 128 + ci) * 64 + co];
    } else if (term <= 4) {
        v = W[((0 * 5 + term) * 128 + ci) * 64 + co];
    } else {
        v = W[((1 * 5 + (term - 4)) * 128 + ci) * 64 + co];
    }
    g_Wcat[kk * 128 + j] = __uint_as_float(f2tf32(v));
}

// ---------------- basis term 0 = X ----------------
__global__ void copy_t0_kernel(const float* __restrict__ x) {
    int i = blockIdx.x * blockDim.x + threadIdx.x;   // float4 index
    if (i < MROWS * FF / 4) {
        int r = i >> 4, f4 = i & 15;
        const float4 v = reinterpret_cast<const float4*>(x)[i];
        *reinterpret_cast<float4*>(&g_basis[(size_t)r * KC + f4 * 4]) = v;
    }
}

// ---------------- sparse propagation ----------------
__global__ void prop_out_kernel(int term_in, int term_out, int term_sub, float alpha) {
    int n  = blockIdx.x % NN;
    int bt = blockIdx.x / NN;
    int f  = threadIdx.x;
    int b0 = g_ptr_dst[n], b1 = g_ptr_dst[n + 1];
    const float* base = g_basis + (size_t)bt * NN * KC + term_in * FF + f;
    float acc = 0.f;
    for (int e = b0; e < b1; e++)
        acc += g_w_dst[e] * __ldg(base + (size_t)g_idx_dst[e] * KC);
    float res = alpha * acc;
    float* orow = g_basis + (size_t)(bt * NN + n) * KC;
    if (term_sub >= 0) res -= orow[term_sub * FF + f];
    orow[term_out * FF + f] = res;
}

__global__ void prop_in_kernel(int term_in, int term_out, int term_sub, float alpha) {
    int n  = blockIdx.x % NN;
    int bt = blockIdx.x / NN;
    int f  = threadIdx.x;
    int b0 = g_ptr_src[n], b1 = g_ptr_src[n + 1];
    const float* base = g_basis + (size_t)bt * NN * KC + term_in * FF + f;
    float acc = 0.f;
    for (int e = b0; e < b1; e++)
        acc += __ldg(base + (size_t)g_idx_src[e] * KC);
    float res = alpha * g_inv_in[n] * acc;
    float* orow = g_basis + (size_t)(bt * NN + n) * KC;
    if (term_sub >= 0) res -= orow[term_sub * FF + f];
    orow[term_out * FF + f] = res;
}

// ---------------- tf32 tensor-core GEMM (192000x576 @ 576x128) + gate + LN ----------------
// CTA: 256 thr / 8 warps, tile 128(M) x 128(N). Warp w owns rows [16w,16w+16),
// full 128 cols => 16 m16n8k8 tiles; z (cols<64) and h (cols>=64) pair up as
// tiles j and j+8 within one thread -> register-only epilogue.
#define TM 128
#define TKC 16
__global__ void __launch_bounds__(256) gemm_tc_kernel(
    const float* __restrict__ bz, const float* __restrict__ bh,
    const float* __restrict__ lng, const float* __restrict__ lnb)
{
    __shared__ uint32_t As[TM][TKC + 1];
    __shared__ uint32_t Bs[TKC][132];

    int tid = threadIdx.x;
    int w = tid >> 5, lane = tid & 31;
    int g = lane >> 2, tg = lane & 3;
    int block_row = blockIdx.x * TM;

    float acc[16][4];
#pragma unroll
    for (int j = 0; j < 16; j++)
#pragma unroll
        for (int i = 0; i < 4; i++) acc[j][i] = 0.f;

    int arow = tid >> 1;            // A-load: 2 threads per row, 8 floats each
    int acol = (tid & 1) * 8;
    int brow = tid >> 4;            // B-load: 16 threads per row, 8 floats each
    int bcol = (tid & 15) * 8;
    const float* aptr = &g_basis[(size_t)(block_row + arow) * KC + acol];
    const float* bptr = &g_Wcat[brow * 128 + bcol];

    for (int k0 = 0; k0 < KC; k0 += TKC) {
        float4 a0 = *reinterpret_cast<const float4*>(aptr + k0);
        float4 a1 = *reinterpret_cast<const float4*>(aptr + k0 + 4);
        As[arow][acol + 0] = f2tf32(a0.x); As[arow][acol + 1] = f2tf32(a0.y);
        As[arow][acol + 2] = f2tf32(a0.z); As[arow][acol + 3] = f2tf32(a0.w);
        As[arow][acol + 4] = f2tf32(a1.x); As[arow][acol + 5] = f2tf32(a1.y);
        As[arow][acol + 6] = f2tf32(a1.z); As[arow][acol + 7] = f2tf32(a1.w);
        float4 b0 = *reinterpret_cast<const float4*>(bptr + k0 * 128);
        float4 b1 = *reinterpret_cast<const float4*>(bptr + k0 * 128 + 4);
        Bs[brow][bcol + 0] = __float_as_uint(b0.x); Bs[brow][bcol + 1] = __float_as_uint(b0.y);
        Bs[brow][bcol + 2] = __float_as_uint(b0.z); Bs[brow][bcol + 3] = __float_as_uint(b0.w);
        Bs[brow][bcol + 4] = __float_as_uint(b1.x); Bs[brow][bcol + 5] = __float_as_uint(b1.y);
        Bs[brow][bcol + 6] = __float_as_uint(b1.z); Bs[brow][bcol + 7] = __float_as_uint(b1.w);
        __syncthreads();

#pragma unroll
        for (int kb = 0; kb < TKC; kb += 8) {
            uint32_t a[4];
            a[0] = As[w * 16 + g][kb + tg];
            a[1] = As[w * 16 + g + 8][kb + tg];
            a[2] = As[w * 16 + g][kb + tg + 4];
            a[3] = As[w * 16 + g + 8][kb + tg + 4];
#pragma unroll
            for (int j = 0; j < 16; j++) {
                uint32_t bb0 = Bs[kb + tg][j * 8 + g];
                uint32_t bb1 = Bs[kb + tg + 4][j * 8 + g];
                mma_tf32(acc[j], a, bb0, bb1);
            }
        }
        __syncthreads();
    }

    // ---- epilogue: gate + LayerNorm, register-resident ----
    // rows: r0 = block_row + 16w + g (acc idx 0,1), r1 = r0 + 8 (acc idx 2,3)
    // thread cols in tile j: j*8 + tg*2 + {0,1}; z tiles j=0..7, h tiles j=8..15.
#pragma unroll
    for (int rs = 0; rs < 2; rs++) {
        int row = block_row + w * 16 + g + rs * 8;
        float gv[8][2];
        float sum = 0.f, sq = 0.f;
#pragma unroll
        for (int j = 0; j < 8; j++) {
#pragma unroll
            for (int s = 0; s < 2; s++) {
                int col = j * 8 + tg * 2 + s;
                float vz = acc[j][rs * 2 + s] + __ldg(bz + col);
                float vh = acc[j + 8][rs * 2 + s] + __ldg(bh + col);
                float z = 1.f / (1.f + expf(-vz));
                float val = fmaxf(0.f, (1.f - z) * tanhf(vh));
                gv[j][s] = val;
                sum += val; sq += val * val;
            }
        }
        // 64 features live across the 4 lanes sharing g (lanes 4g..4g+3)
        sum += __shfl_xor_sync(0xffffffffu, sum, 1);
        sq  += __shfl_xor_sync(0xffffffffu, sq, 1);
        sum += __shfl_xor_sync(0xffffffffu, sum, 2);
        sq  += __shfl_xor_sync(0xffffffffu, sq, 2);
        float mu = sum * (1.f / 64.f);
        float var = fmaxf(sq * (1.f / 64.f) - mu * mu, 0.f);
        float rstd = rsqrtf(var + LN_EPS);
        float* orow = g_hn + (size_t)row * FF;
#pragma unroll
        for (int j = 0; j < 8; j++) {
            int col = j * 8 + tg * 2;
            float2 o;
            o.x = (gv[j][0] - mu) * rstd * __ldg(lng + col)     + __ldg(lnb + col);
            o.y = (gv[j][1] - mu) * rstd * __ldg(lng + col + 1) + __ldg(lnb + col + 1);
            *reinterpret_cast<float2*>(orow + col) = o;
        }
    }
}

// ---------------- final linear head ----------------
__global__ void out_init_kernel(float* __restrict__ out, const float* __restrict__ lb) {
    int i = threadIdx.x;
    if (i < BB * CC) out[i] = lb[i % CC];
}

#define CH 1024
__global__ void __launch_bounds__(256) final_linear_kernel(
    const float* __restrict__ lin_w, float* __restrict__ out)
{
    __shared__ float ws[CC][CH];
    __shared__ float red[8][CC];
    int base = blockIdx.x * CH;   // 750 blocks * 1024 = 768000
    int tid = threadIdx.x;
    for (int i = tid; i < CC * CH; i += 256) {
        int c = i / CH, o = i % CH;
        ws[c][o] = lin_w[(size_t)c * LDIM + base + o];
    }
    __syncthreads();
    int w = tid >> 5, lane = tid & 31;
    for (int b = 0; b < BB; b++) {
        float a[CC];
#pragma unroll
        for (int c = 0; c < CC; c++) a[c] = 0.f;
        const float* hb = g_hn + (size_t)b * LDIM + base;
        for (int i = tid; i < CH; i += 256) {
            float hv = hb[i];
#pragma unroll
            for (int c = 0; c < CC; c++) a[c] += hv * ws[c][i];
        }
#pragma unroll
        for (int o = 16; o; o >>= 1)
#pragma unroll
            for (int c = 0; c < CC; c++) a[c] += __shfl_down_sync(0xffffffffu, a[c], o);
        if (lane == 0)
#pragma unroll
            for (int c = 0; c < CC; c++) red[w][c] = a[c];
        __syncthreads();
        if (tid < CC) {
            float s = 0.f;
#pragma unroll
            for (int ww = 0; ww < 8; ww++) s += red[ww][tid];
            atomicAdd(&out[b * CC + tid], s);
        }
        __syncthreads();
    }
}

// ---------------- launch ----------------
extern "C" void kernel_launch(void* const* d_in, const int* in_sizes, int n_in,
                              void* d_out, int out_size) {
    const float* x    = (const float*)d_in[0];
    const int*   ei   = (const int*)d_in[1];
    const float* Wz   = (const float*)d_in[2];
    const float* bz   = (const float*)d_in[3];
    // d_in[4], d_in[5] = W_r, b_r -> dead code (h0 == 0)
    const float* Wh   = (const float*)d_in[6];
    const float* bh   = (const float*)d_in[7];
    const float* lng  = (const float*)d_in[8];
    const float* lnb  = (const float*)d_in[9];
    const float* linw = (const float*)d_in[10];
    const float* linb = (const float*)d_in[11];
    float* out = (float*)d_out;

    init_counts_kernel<<<(NN + 255) / 256, 256>>>();
    degree_kernel<<<(EE + 255) / 256, 256>>>(ei);
    scan_kernel<<<1, 256>>>();
    fill_kernel<<<(EE + 255) / 256, 256>>>(ei);
    wcat_kernel<<<(KC * 128 + 255) / 256, 256>>>(Wz, Wh);
    copy_t0_kernel<<<(MROWS * FF / 4 + 255) / 256, 256>>>(x);

    int nb = BTOT * NN;
    // terms: 0=X, 1..4 = out-chain, 5..8 = in-chain (in-chain Tx0 history uses out-chain terms)
    prop_out_kernel<<<nb, FF>>>(0, 1, -1, 1.0f);
    prop_in_kernel <<<nb, FF>>>(0, 5, -1, 1.0f);
    prop_out_kernel<<<nb, FF>>>(1, 2, 0, 2.0f);
    prop_in_kernel <<<nb, FF>>>(5, 6, 0, 2.0f);
    prop_out_kernel<<<nb, FF>>>(2, 3, 1, 2.0f);
    prop_in_kernel <<<nb, FF>>>(6, 7, 1, 2.0f);
    prop_out_kernel<<<nb, FF>>>(3, 4, 2, 2.0f);
    prop_in_kernel <<<nb, FF>>>(7, 8, 2, 2.0f);

    gemm_tc_kernel<<<MROWS / TM, 256>>>(bz, bh, lng, lnb);

    out_init_kernel<<<1, 256>>>(out, linb);
    final_linear_kernel<<<LDIM / CH, 256>>>(linw, out);
}